// round 17
// baseline (speedup 1.0000x reference)
#include <cuda_runtime.h>
#include <cstdint>

// ---------------------------------------------------------------------------
// BSplineBasis: out[N,60] = cubic B-spline basis of min-max-normalized x.
// <=4 of 60 outputs per row are nonzero (degree 3). 252MB output -> HBM
// write-stream bound: row kernel runs at ~6.2 TB/s logical writes (ceiling).
//
// R17 = R16 with 512-thread blocks (halves per-block prologue + scheduling
// overhead; the warp-level write sweep is block-size-agnostic):
//  - minmax_partials (512 blocks): pure grid-stride partial min/max, plain
//    overwriting stores; block 0 concurrently builds the knot-only 186-entry
//    guarded reciprocal table. No atomics / tickets / fences -- the kernel
//    boundary provides visibility. Deterministic across graph replays.
//  - bspline (2048 blocks x 512): each block reduces the 512 partials
//    (1 broadcast L2 load/thread + warp reduce, bit-identical everywhere),
//    divide-free Cox-de Boor, then the minimal-wavefront coalesced sweep:
//    each warp writes its 32 rows = 480 contiguous float4 exactly once
//    (q0 via SHFL, window via one predicated LDS.128, streaming STG.128).
// ---------------------------------------------------------------------------

#define NUM_KNOTS 64
#define DEGREE 3
#define NBASIS (NUM_KNOTS - DEGREE - 1)   // 60
#define ROW_VEC4 (NBASIS / 4)             // 15 float4 per row
#define BLOCK_THREADS 512
#define NWARPS (BLOCK_THREADS / 32)       // 16
#define NPART 512                          // == BLOCK_THREADS (1 partial/thread)
// inv table layout: d=1 at [0,63), d=2 at [63,125), d=3 at [125,186)
#define INV1 0
#define INV2 63
#define INV3 125
#define INV_TOTAL 186

__device__ unsigned g_pmin[NPART];
__device__ unsigned g_pmax[NPART];
__device__ float g_inv[INV_TOTAL];

__device__ __forceinline__ unsigned fmap(float f) {
    unsigned u = __float_as_uint(f);
    return (u & 0x80000000u) ? ~u : (u | 0x80000000u);
}
__device__ __forceinline__ float funmap(unsigned u) {
    u = (u & 0x80000000u) ? (u & 0x7FFFFFFFu) : ~u;
    return __uint_as_float(u);
}

__global__ void __launch_bounds__(BLOCK_THREADS)
minmax_partials_kernel(const float* __restrict__ x,
                       const float* __restrict__ knots, int n) {
    __shared__ unsigned smin[NWARPS], smax[NWARPS];

    // Block 0 builds the knot-only reciprocal table (independent of min/max).
    if (blockIdx.x == 0 && threadIdx.x < INV_TOTAL) {
        int f = threadIdx.x;
        int d, j;
        if (f < INV2)      { d = 1; j = f; }
        else if (f < INV3) { d = 2; j = f - INV2; }
        else               { d = 3; j = f - INV3; }
        float den = __ldg(&knots[j + d]) - __ldg(&knots[j]);
        g_inv[f] = (den > 0.0f) ? __fdiv_rn(1.0f, den) : 0.0f;
    }

    int tid = blockIdx.x * blockDim.x + threadIdx.x;
    int stride = gridDim.x * blockDim.x;
    int lane = threadIdx.x & 31;
    int wid  = threadIdx.x >> 5;

    unsigned lmin = 0xFFFFFFFFu;
    unsigned lmax = 0x00000000u;

    int n4 = n >> 2;
    const float4* x4 = (const float4*)x;
    for (int i = tid; i < n4; i += stride) {
        float4 v = x4[i];
        unsigned a = fmap(v.x), b = fmap(v.y), c = fmap(v.z), d = fmap(v.w);
        lmin = min(lmin, min(min(a, b), min(c, d)));
        lmax = max(lmax, max(max(a, b), max(c, d)));
    }
    for (int i = (n4 << 2) + tid; i < n; i += stride) {
        unsigned a = fmap(x[i]);
        lmin = min(lmin, a);
        lmax = max(lmax, a);
    }

    #pragma unroll
    for (int off = 16; off > 0; off >>= 1) {
        lmin = min(lmin, __shfl_xor_sync(0xFFFFFFFFu, lmin, off));
        lmax = max(lmax, __shfl_xor_sync(0xFFFFFFFFu, lmax, off));
    }
    if (lane == 0) { smin[wid] = lmin; smax[wid] = lmax; }
    __syncthreads();
    if (wid == 0) {
        lmin = (lane < NWARPS) ? smin[lane] : 0xFFFFFFFFu;
        lmax = (lane < NWARPS) ? smax[lane] : 0x00000000u;
        #pragma unroll
        for (int off = NWARPS / 2; off > 0; off >>= 1) {
            lmin = min(lmin, __shfl_xor_sync(0xFFFFFFFFu, lmin, off));
            lmax = max(lmax, __shfl_xor_sync(0xFFFFFFFFu, lmax, off));
        }
        if (lane == 0) {
            g_pmin[blockIdx.x] = lmin;   // unconditional overwrite each run
            g_pmax[blockIdx.x] = lmax;
        }
    }
}

__global__ void __launch_bounds__(BLOCK_THREADS, 4)
bspline_kernel(const float* __restrict__ x,
               const float* __restrict__ knots,
               float* __restrict__ out, int n) {
    __shared__ float t[NUM_KNOTS];
    __shared__ float inv[INV_TOTAL];
    __shared__ unsigned rmin[NWARPS], rmax[NWARPS];
    __shared__ __align__(16) float4 sfw[2 * BLOCK_THREADS];  // f0,f1 packed

    int tid  = threadIdx.x;
    int lane = tid & 31;
    int wid  = tid >> 5;

    // ---- prologue: constants + per-block partials reduction ----
    if (tid < NUM_KNOTS) t[tid] = __ldg(&knots[tid]);
    if (tid < INV_TOTAL) inv[tid] = g_inv[tid];

    {
        // NPART == BLOCK_THREADS: exactly one partial per thread.
        unsigned a = __ldcg(&g_pmin[tid]);
        unsigned b = __ldcg(&g_pmax[tid]);
        #pragma unroll
        for (int off = 16; off > 0; off >>= 1) {
            a = min(a, __shfl_xor_sync(0xFFFFFFFFu, a, off));
            b = max(b, __shfl_xor_sync(0xFFFFFFFFu, b, off));
        }
        if (lane == 0) { rmin[wid] = a; rmax[wid] = b; }
    }
    __syncthreads();

    unsigned bmin = 0xFFFFFFFFu, bmax = 0u;
    #pragma unroll
    for (int w = 0; w < NWARPS; ++w) {
        bmin = min(bmin, rmin[w]);
        bmax = max(bmax, rmax[w]);
    }
    float xmin = funmap(bmin);
    float xmax = funmap(bmax);
    // Bit-exact reference denominator (IEEE rn ops; identical in every block).
    float nden = __fadd_rn(__fsub_rn(xmax, xmin), 1e-8f);

    int row = blockIdx.x * BLOCK_THREADS + tid;

    float4 f0 = make_float4(0.f, 0.f, 0.f, 0.f);
    float4 f1 = make_float4(0.f, 0.f, 0.f, 0.f);
    int q0 = -2;   // never matches for inactive rows

    if (row < n) {
        // Bit-exact reference normalization (feeds the half-open interval
        // tests; the max element rounds to xn==1.0f -> all-zero row).
        float xn = __fdiv_rn(__fsub_rn(x[row], xmin), nden);

        // Span search: analytic guess + exact fixup.
        int i = DEGREE + (int)(xn * (float)(NUM_KNOTS - 2 * DEGREE - 1));
        i = max(DEGREE, min(i, NUM_KNOTS - DEGREE - 2));
        while (i > DEGREE && xn < t[i]) --i;
        while (i < NUM_KNOTS - DEGREE - 2 && xn >= t[i + 1]) ++i;

        float seed = (xn >= t[i] && xn < t[i + 1]) ? 1.0f : 0.0f;

        // Divide-free Cox-de Boor recursion on the 4-wide active window.
        float Bcur[DEGREE + 1];
        Bcur[0] = seed;
        #pragma unroll
        for (int d = 1; d <= DEGREE; ++d) {
            const int base = (d == 1) ? INV1 : (d == 2) ? INV2 : INV3;
            float Bnew[DEGREE + 1];
            #pragma unroll
            for (int k = 0; k <= d; ++k) {
                int j = i - d + k;
                float L = (xn - t[j])         * inv[base + j];
                float R = (t[j + d + 1] - xn) * inv[base + j + 1];
                float bl = (k >= 1) ? Bcur[k - 1] : 0.0f;
                float br = (k <= d - 1) ? Bcur[k] : 0.0f;
                Bnew[k] = L * bl + R * br;
            }
            #pragma unroll
            for (int k = 0; k <= d; ++k) Bcur[k] = Bnew[k];
        }

        int c0 = i - DEGREE;          // [0, 56]
        q0 = c0 >> 2;                 // [0, 14]
        int r = c0 & 3;
        f0.x = (r == 0) ? Bcur[0] : 0.f;
        f0.y = (r == 0) ? Bcur[1] : (r == 1) ? Bcur[0] : 0.f;
        f0.z = (r == 0) ? Bcur[2] : (r == 1) ? Bcur[1] : (r == 2) ? Bcur[0] : 0.f;
        f0.w = (r == 0) ? Bcur[3] : (r == 1) ? Bcur[2] : (r == 2) ? Bcur[1] : Bcur[0];
        f1.x = (r == 1) ? Bcur[3] : (r == 2) ? Bcur[2] : (r == 3) ? Bcur[1] : 0.f;
        f1.y = (r == 2) ? Bcur[3] : (r == 3) ? Bcur[2] : 0.f;
        f1.z = (r == 3) ? Bcur[3] : 0.f;
        f1.w = 0.f;
    }

    // Stage window data (f0/f1 packed); q0 distributed via SHFL in the sweep.
    sfw[2 * tid]     = f0;
    sfw[2 * tid + 1] = f1;
    __syncwarp();    // consumers are warp-local only

    // ---- single coalesced write sweep: warp's 32 rows = 480 float4 ----
    int wrow0 = blockIdx.x * BLOCK_THREADS + (wid << 5);
    float4* ospan = (float4*)(out + (size_t)wrow0 * NBASIS);
    const int sbase = wid << 5;
    const float4 z4 = make_float4(0.f, 0.f, 0.f, 0.f);

    if (wrow0 + 32 <= n) {
        #pragma unroll
        for (int s = 0; s < ROW_VEC4; ++s) {
            int idx = s * 32 + lane;          // [0, 480)
            int src = idx / ROW_VEC4;         // owning local row [0, 32)
            int q   = idx - src * ROW_VEC4;   // float4 index within row
            int q0s = __shfl_sync(0xFFFFFFFFu, q0, src);   // register, no LDS
            unsigned dq = (unsigned)(q - q0s);
            float4 v = z4;
            if (dq <= 1u) v = sfw[2 * (sbase + src) + dq]; // predicated LDS.128
            __stcs(&ospan[idx], v);                        // streaming store
        }
    } else if (wrow0 < n) {
        int valid4 = (n - wrow0) * ROW_VEC4;
        for (int idx = lane; idx < valid4; idx += 32) {
            int src = idx / ROW_VEC4;
            int q   = idx - src * ROW_VEC4;
            int q0s = __shfl_sync(0xFFFFFFFFu, q0, src);
            unsigned dq = (unsigned)(q - q0s);
            float4 v = z4;
            if (dq <= 1u) v = sfw[2 * (sbase + src) + dq];
            __stcs(&ospan[idx], v);
        }
    }
}

extern "C" void kernel_launch(void* const* d_in, const int* in_sizes, int n_in,
                              void* d_out, int out_size) {
    const float* x     = (const float*)d_in[0];
    const float* knots = (const float*)d_in[1];
    float* out = (float*)d_out;
    int n = in_sizes[0];   // N_ROWS (x is [N,1])

    minmax_partials_kernel<<<NPART, BLOCK_THREADS>>>(x, knots, n);

    int blocks = (n + BLOCK_THREADS - 1) / BLOCK_THREADS;
    bspline_kernel<<<blocks, BLOCK_THREADS>>>(x, knots, out, n);
}